// round 9
// baseline (speedup 1.0000x reference)
#include <cuda_runtime.h>
#include <math.h>

// MaxNormPooling2D: quaternion max-norm 2x2 pooling, stride 2, VALID.
// Inputs: x0..x3 each (B=16, H=128, W=128, C=64) fp32, NHWC.
// Output: concatenated (out0..out3), each (16, 64, 64, 64) fp32.
//
// R8: DRAM-ceiling-bound (~5.97 TB/s). Best prior kernel = persistent
// single-wave (R6, 53.18us) but its 444-block grid-stride split was ragged
// (9 vs 10 iterations -> ~0.6us drain skew). This round: PERFECTLY balanced
// single-wave split — 512 blocks x 256 threads (4 blocks/SM, needs <=64
// regs) x exactly 16 float2-iterations per thread. No partial wave, no
// ragged tail, no streaming cache hints.

#define B_  16
#define H_  128
#define W_  128
#define C_  64
#define HO_ 64
#define WO_ 64

// float2 granularity: 32 float2 groups per pixel channel dim (C=64/2)
#define C2_ 32
#define NWORK_TOTAL (B_ * HO_ * WO_ * C2_)      // 2,097,152 work items
#define OUT_COMP_F2 (B_ * HO_ * WO_ * C_ / 2)   // 2,097,152

#define THREADS_ 256
#define GRID_    512
#define STRIDE_  (GRID_ * THREADS_)              // 131,072
#define ITERS_   (NWORK_TOTAL / STRIDE_)         // 16, exact

__global__ __launch_bounds__(THREADS_, 4) void maxnorm_pool_kernel(
    const float2* __restrict__ x0,
    const float2* __restrict__ x1,
    const float2* __restrict__ x2,
    const float2* __restrict__ x3,
    float2* __restrict__ out)
{
    int t = blockIdx.x * THREADS_ + threadIdx.x;

#pragma unroll 1
    for (int it = 0; it < ITERS_; ++it, t += STRIDE_) {
        int c2  = t & (C2_ - 1);
        int pix = t >> 5;             // b*HO*WO + ho*WO + wo
        int wo  = pix & (WO_ - 1);
        int ho  = (pix >> 6) & (HO_ - 1);
        int b   = pix >> 12;

        int h0 = ho << 1;
        int w0 = wo << 1;

        // input index in float2 units: ((b*H + h)*W + w)*C2 + c2
        // window positions in row-major order: (0,0),(0,1),(1,0),(1,1)
        int base = ((b * H_ + h0) * W_ + w0) * C2_ + c2;
        int off[4];
        off[0] = base;
        off[1] = base + C2_;          // dw=1
        off[2] = base + W_ * C2_;     // dh=1
        off[3] = base + W_ * C2_ + C2_;

        // best norm per lane (norms >= 0, so -1 guarantees p=0 wins first ->
        // first-max tie-break like TF/argmax)
        float2 bn = make_float2(-1.f, -1.f);
        float2 o0, o1, o2, o3;

#pragma unroll
        for (int p = 0; p < 4; ++p) {
            float2 a0 = x0[off[p]];
            float2 a1 = x1[off[p]];
            float2 a2 = x2[off[p]];
            float2 a3 = x3[off[p]];

            // sequential sum order x0^2 + x1^2 + x2^2 + x3^2, then sqrt —
            // matches the reference's comparison domain for tie behavior.
            float nx = sqrtf(a0.x * a0.x + a1.x * a1.x + a2.x * a2.x + a3.x * a3.x);
            float ny = sqrtf(a0.y * a0.y + a1.y * a1.y + a2.y * a2.y + a3.y * a3.y);

            if (nx > bn.x) { bn.x = nx; o0.x = a0.x; o1.x = a1.x; o2.x = a2.x; o3.x = a3.x; }
            if (ny > bn.y) { bn.y = ny; o0.y = a0.y; o1.y = a1.y; o2.y = a2.y; o3.y = a3.y; }
        }

        int obase = pix * C2_ + c2;   // within one component, float2 units
        out[obase]                   = o0;
        out[obase +     OUT_COMP_F2] = o1;
        out[obase + 2 * OUT_COMP_F2] = o2;
        out[obase + 3 * OUT_COMP_F2] = o3;
    }
}

extern "C" void kernel_launch(void* const* d_in, const int* in_sizes, int n_in,
                              void* d_out, int out_size)
{
    const float2* x0 = (const float2*)d_in[0];
    const float2* x1 = (const float2*)d_in[1];
    const float2* x2 = (const float2*)d_in[2];
    const float2* x3 = (const float2*)d_in[3];
    float2* out = (float2*)d_out;

    maxnorm_pool_kernel<<<GRID_, THREADS_>>>(x0, x1, x2, x3, out);
}

// round 10
// speedup vs baseline: 1.1499x; 1.1499x over previous
#include <cuda_runtime.h>
#include <math.h>

// MaxNormPooling2D: quaternion max-norm 2x2 pooling, stride 2, VALID.
// Inputs: x0..x3 each (B=16, H=128, W=128, C=64) fp32, NHWC.
// Output: concatenated (out0..out3), each (16, 64, 64, 64) fp32.
//
// R9: model = DRAM% tracks (occupancy x load width). float4 loads at 4
// blocks/SM beats all prior configs on outstanding-bytes. To fit 64 regs
// (4 blocks x 256 thr x 64 = full 64K regfile), the argmax loop carries
// only the winning window INDEX per component (4 regs) instead of the 16
// selected values; winners are re-fetched afterward via scalar loads that
// hit L1 (lines just touched, L1 at 19% with huge headroom). DRAM traffic
// unchanged. Persistent single-wave 592-block launch.

#define B_  16
#define H_  128
#define W_  128
#define C_  64
#define HO_ 64
#define WO_ 64

#define C4_ 16
#define NWORK_TOTAL (B_ * HO_ * WO_ * C4_)      // 1,048,576 float4 items
#define OUT_COMP_F4 (B_ * HO_ * WO_ * C_ / 4)   // 1,048,576

#define THREADS_ 256
#define NSM_     148
#define BLKS_PER_SM_ 4
#define GRID_    (NSM_ * BLKS_PER_SM_)           // 592 persistent blocks
#define STRIDE_  (GRID_ * THREADS_)              // 151,552

__global__ __launch_bounds__(THREADS_, BLKS_PER_SM_) void maxnorm_pool_kernel(
    const float4* __restrict__ x0,
    const float4* __restrict__ x1,
    const float4* __restrict__ x2,
    const float4* __restrict__ x3,
    float4* __restrict__ out)
{
    // scalar views for the winner re-fetch (L1 hits)
    const float* __restrict__ f0 = (const float*)x0;
    const float* __restrict__ f1 = (const float*)x1;
    const float* __restrict__ f2 = (const float*)x2;
    const float* __restrict__ f3 = (const float*)x3;

    for (int t = blockIdx.x * THREADS_ + threadIdx.x; t < NWORK_TOTAL; t += STRIDE_) {
        int c4  = t & (C4_ - 1);
        int pix = t >> 4;             // b*HO*WO + ho*WO + wo
        int wo  = pix & (WO_ - 1);
        int ho  = (pix >> 6) & (HO_ - 1);
        int b   = pix >> 12;

        int h0 = ho << 1;
        int w0 = wo << 1;

        // input index in float4 units: ((b*H + h)*W + w)*C4 + c4
        int base = ((b * H_ + h0) * W_ + w0) * C4_ + c4;

        // best norm + best window index per component.
        // norms >= 0, bn = -1 => p=0 wins first -> first-max tie-break
        // (strict >), matching TF/argmax.
        float bnx = -1.f, bny = -1.f, bnz = -1.f, bnw = -1.f;
        int bix = 0, biy = 0, biz = 0, biw = 0;

#pragma unroll
        for (int p = 0; p < 4; ++p) {
            // window positions row-major: (0,0),(0,1),(1,0),(1,1)
            int off = base + (p & 1) * C4_ + (p >> 1) * (W_ * C4_);
            float4 a0 = x0[off];
            float4 a1 = x1[off];
            float4 a2 = x2[off];
            float4 a3 = x3[off];

            // sequential sum order x0^2 + x1^2 + x2^2 + x3^2, then sqrt —
            // matches the reference's comparison domain for tie behavior.
            float nx = sqrtf(a0.x * a0.x + a1.x * a1.x + a2.x * a2.x + a3.x * a3.x);
            float ny = sqrtf(a0.y * a0.y + a1.y * a1.y + a2.y * a2.y + a3.y * a3.y);
            float nz = sqrtf(a0.z * a0.z + a1.z * a1.z + a2.z * a2.z + a3.z * a3.z);
            float nw = sqrtf(a0.w * a0.w + a1.w * a1.w + a2.w * a2.w + a3.w * a3.w);

            if (nx > bnx) { bnx = nx; bix = p; }
            if (ny > bny) { bny = ny; biy = p; }
            if (nz > bnz) { bnz = nz; biz = p; }
            if (nw > bnw) { bnw = nw; biw = p; }
        }

        // Re-fetch the winning elements (same memory, unmodified -> exact
        // values; all L1 hits). Float offset of component c at window p:
        // (base + step(p)) * 4 + c.
        int sx = (base + (bix & 1) * C4_ + (bix >> 1) * (W_ * C4_)) * 4;
        int sy = (base + (biy & 1) * C4_ + (biy >> 1) * (W_ * C4_)) * 4 + 1;
        int sz = (base + (biz & 1) * C4_ + (biz >> 1) * (W_ * C4_)) * 4 + 2;
        int sw = (base + (biw & 1) * C4_ + (biw >> 1) * (W_ * C4_)) * 4 + 3;

        float4 o0, o1, o2, o3;
        o0.x = f0[sx]; o0.y = f0[sy]; o0.z = f0[sz]; o0.w = f0[sw];
        o1.x = f1[sx]; o1.y = f1[sy]; o1.z = f1[sz]; o1.w = f1[sw];
        o2.x = f2[sx]; o2.y = f2[sy]; o2.z = f2[sz]; o2.w = f2[sw];
        o3.x = f3[sx]; o3.y = f3[sy]; o3.z = f3[sz]; o3.w = f3[sw];

        int obase = pix * C4_ + c4;   // within one component, float4 units
        out[obase]                   = o0;
        out[obase +     OUT_COMP_F4] = o1;
        out[obase + 2 * OUT_COMP_F4] = o2;
        out[obase + 3 * OUT_COMP_F4] = o3;
    }
}

extern "C" void kernel_launch(void* const* d_in, const int* in_sizes, int n_in,
                              void* d_out, int out_size)
{
    const float4* x0 = (const float4*)d_in[0];
    const float4* x1 = (const float4*)d_in[1];
    const float4* x2 = (const float4*)d_in[2];
    const float4* x3 = (const float4*)d_in[3];
    float4* out = (float4*)d_out;

    maxnorm_pool_kernel<<<GRID_, THREADS_>>>(x0, x1, x2, x3, out);
}